// round 1
// baseline (speedup 1.0000x reference)
#include <cuda_runtime.h>
#include <math.h>

// Problem dims
#define S_DIM 256   // sequence_num (attention axis, LN axis)
#define R_DIM 256   // residue columns (batch for attention)
#define C_DIM 256   // channels
#define H_DIM 8
#define D_DIM 32
#define HD_DIM 256
#define MTOT (R_DIM * S_DIM)   // 65536 rows for the big GEMMs
#define EPS 1e-5f

// -------- scratch (device globals; no cudaMalloc allowed) --------
__device__ float g_xn [(size_t)MTOT * C_DIM];   // normalized x, [r][s][c]
__device__ float g_q  [(size_t)MTOT * HD_DIM];
__device__ float g_k  [(size_t)MTOT * HD_DIM];
__device__ float g_v  [(size_t)MTOT * HD_DIM];
__device__ float g_g  [(size_t)MTOT * HD_DIM];  // sigmoid gate
__device__ float g_ctx[(size_t)MTOT * HD_DIM];  // gated attention output

// ============================================================
// Kernel 1: LayerNorm over the s axis (per (r,c)), writes xn[r][s][c]
// msa layout: [s][r][c] -> element at s*65536 + r*256 + c
// ============================================================
__global__ void ln_kernel(const float* __restrict__ msa,
                          const float* __restrict__ lnw,
                          const float* __restrict__ lnb)
{
    int r = blockIdx.x;
    int c = threadIdx.x;
    const float* p = msa + r * C_DIM + c;

    float sum = 0.f, sq = 0.f;
    #pragma unroll 4
    for (int s = 0; s < S_DIM; s++) {
        float v = p[s * (R_DIM * C_DIM)];
        sum += v; sq += v * v;
    }
    float mu  = sum * (1.f / S_DIM);
    float var = sq * (1.f / S_DIM) - mu * mu;
    float rstd = rsqrtf(var + EPS);

    float* o = g_xn + (size_t)r * (S_DIM * C_DIM) + c;
    #pragma unroll 4
    for (int s = 0; s < S_DIM; s++) {
        float v = p[s * (R_DIM * C_DIM)];
        o[s * C_DIM] = (v - mu) * rstd * lnw[s] + lnb[s];
    }
}

// ============================================================
// Kernel 2: fused Q/K/V/G projections.
// A = g_xn [65536 x 256], B = W{q,k,v,g} [256 x 256], z selects matrix.
// 128x128 tile, BK=8, 256 threads, 8x8 per-thread micro-tile.
// ============================================================
__global__ void __launch_bounds__(256) qkvg_gemm(
    const float* __restrict__ Wq, const float* __restrict__ Wk,
    const float* __restrict__ Wv, const float* __restrict__ Wg,
    const float* __restrict__ bg)
{
    const float* W; float* O; bool is_gate = false;
    switch (blockIdx.z) {
        case 0:  W = Wq; O = g_q; break;
        case 1:  W = Wk; O = g_k; break;
        case 2:  W = Wv; O = g_v; break;
        default: W = Wg; O = g_g; is_gate = true; break;
    }

    __shared__ float As[8][128];
    __shared__ float Bs[8][128];

    int tid = threadIdx.x;
    int tx = tid & 15;           // 0..15 -> n
    int ty = tid >> 4;           // 0..15 -> m
    int block_m = blockIdx.y * 128;
    int block_n = blockIdx.x * 128;

    int a_row = tid >> 1;            // 0..127
    int a_col = (tid & 1) * 4;       // 0 or 4
    int b_row = tid >> 5;            // 0..7
    int b_col = (tid & 31) * 4;      // 0..124

    float acc[8][8];
    #pragma unroll
    for (int i = 0; i < 8; i++)
        #pragma unroll
        for (int j = 0; j < 8; j++) acc[i][j] = 0.f;

    for (int k0 = 0; k0 < 256; k0 += 8) {
        float4 av = *(const float4*)(g_xn + (size_t)(block_m + a_row) * 256 + k0 + a_col);
        As[a_col + 0][a_row] = av.x;
        As[a_col + 1][a_row] = av.y;
        As[a_col + 2][a_row] = av.z;
        As[a_col + 3][a_row] = av.w;
        *(float4*)(&Bs[b_row][b_col]) =
            *(const float4*)(W + (k0 + b_row) * 256 + block_n + b_col);
        __syncthreads();

        #pragma unroll
        for (int kk = 0; kk < 8; kk++) {
            float a[8], b[8];
            *(float4*)(a)     = *(const float4*)(&As[kk][ty * 8]);
            *(float4*)(a + 4) = *(const float4*)(&As[kk][ty * 8 + 4]);
            *(float4*)(b)     = *(const float4*)(&Bs[kk][tx * 8]);
            *(float4*)(b + 4) = *(const float4*)(&Bs[kk][tx * 8 + 4]);
            #pragma unroll
            for (int i = 0; i < 8; i++)
                #pragma unroll
                for (int j = 0; j < 8; j++)
                    acc[i][j] += a[i] * b[j];
        }
        __syncthreads();
    }

    // epilogue
    int n0 = block_n + tx * 8;
    #pragma unroll
    for (int i = 0; i < 8; i++) {
        int m = block_m + ty * 8 + i;
        float* orow = O + (size_t)m * 256 + n0;
        float vals[8];
        #pragma unroll
        for (int j = 0; j < 8; j++) {
            float t = acc[i][j];
            if (is_gate) {
                t += bg[n0 + j];
                t = 1.f / (1.f + __expf(-t));
            }
            vals[j] = t;
        }
        *(float4*)(orow)     = *(float4*)(vals);
        *(float4*)(orow + 4) = *(float4*)(vals + 4);
    }
}

// ============================================================
// Kernel 3: attention per (h, r). 256 threads.
// SMEM: K[256][32], V[256][32], Q[64][33], logits[64][257], reductions.
// ============================================================
#define QS_PAD 33
#define LS_PAD 257
#define ATTN_SMEM ((256*32 + 256*32 + 64*QS_PAD + 64*LS_PAD + 256 + 64) * 4)

__global__ void __launch_bounds__(256) attn_kernel()
{
    extern __shared__ float sm[];
    float* Ks  = sm;                       // 8192
    float* Vs  = Ks + 256 * 32;            // 8192
    float* Qs  = Vs + 256 * 32;            // 64*33
    float* Ls  = Qs + 64 * QS_PAD;         // 64*257
    float* Red = Ls + 64 * LS_PAD;         // 256
    float* Row = Red + 256;                // 64

    int h = blockIdx.x;
    int r = blockIdx.y;
    int tid = threadIdx.x;

    const int base = (r * S_DIM) * HD_DIM + h * D_DIM;
    const float* qb = g_q + base;
    const float* kb = g_k + base;
    const float* vb = g_v + base;
    const float* gb = g_g + base;

    // load K, V tiles (256 rows x 32 floats each)
    for (int idx = tid; idx < 256 * 8; idx += 256) {
        int row = idx >> 3, f = idx & 7;
        ((float4*)Ks)[row * 8 + f] = *(const float4*)(kb + row * HD_DIM + f * 4);
        ((float4*)Vs)[row * 8 + f] = *(const float4*)(vb + row * HD_DIM + f * 4);
    }
    __syncthreads();

    const float scale = 0.17677669529663687f;  // 1/sqrt(32)
    int qi = tid & 63;
    int jg = tid >> 6;   // 0..3

    for (int rb = 0; rb < 4; rb++) {
        int q0 = rb * 64;
        // stage Q row-block
        for (int idx = tid; idx < 64 * 32; idx += 256) {
            int row = idx >> 5, d = idx & 31;
            Qs[row * QS_PAD + d] = qb[(q0 + row) * HD_DIM + d];
        }
        __syncthreads();

        float qreg[32];
        #pragma unroll
        for (int d = 0; d < 32; d++) qreg[d] = Qs[qi * QS_PAD + d];

        // phase 1: logits + row max (each thread: 64 j's for its qi)
        float lmax = -1e30f;
        for (int j = jg * 64; j < jg * 64 + 64; j++) {
            const float4* kr = (const float4*)(Ks + j * 32);
            float d0 = 0.f, d1 = 0.f, d2 = 0.f, d3 = 0.f;
            #pragma unroll
            for (int f = 0; f < 8; f += 4) {
                float4 k0v = kr[f], k1v = kr[f+1], k2v = kr[f+2], k3v = kr[f+3];
                d0 += qreg[f*4+0]*k0v.x + qreg[f*4+1]*k0v.y + qreg[f*4+2]*k0v.z + qreg[f*4+3]*k0v.w;
                d1 += qreg[f*4+4]*k1v.x + qreg[f*4+5]*k1v.y + qreg[f*4+6]*k1v.z + qreg[f*4+7]*k1v.w;
                d2 += qreg[f*4+8]*k2v.x + qreg[f*4+9]*k2v.y + qreg[f*4+10]*k2v.z + qreg[f*4+11]*k2v.w;
                d3 += qreg[f*4+12]*k3v.x + qreg[f*4+13]*k3v.y + qreg[f*4+14]*k3v.z + qreg[f*4+15]*k3v.w;
            }
            float dot = ((d0 + d1) + (d2 + d3)) * scale;
            Ls[qi * LS_PAD + j] = dot;
            lmax = fmaxf(lmax, dot);
        }
        Red[jg * 64 + qi] = lmax;
        __syncthreads();
        if (tid < 64) {
            float m = fmaxf(fmaxf(Red[tid], Red[64 + tid]),
                            fmaxf(Red[128 + tid], Red[192 + tid]));
            Row[tid] = m;
        }
        __syncthreads();

        // phase 2: exp + row sum
        float rowmax = Row[qi];
        float lsum = 0.f;
        for (int j = jg * 64; j < jg * 64 + 64; j++) {
            float p = __expf(Ls[qi * LS_PAD + j] - rowmax);
            Ls[qi * LS_PAD + j] = p;
            lsum += p;
        }
        Red[jg * 64 + qi] = lsum;
        __syncthreads();
        if (tid < 64) {
            float s = Red[tid] + Red[64 + tid] + Red[128 + tid] + Red[192 + tid];
            Row[tid] = 1.f / s;
        }
        __syncthreads();

        // phase 3: AV. thread handles (qi, 8 d's)
        int dg = jg;
        float acc[8];
        #pragma unroll
        for (int u = 0; u < 8; u++) acc[u] = 0.f;
        for (int j = 0; j < 256; j++) {
            float p = Ls[qi * LS_PAD + j];
            const float4* vr = (const float4*)(Vs + j * 32 + dg * 8);
            float4 v0 = vr[0], v1 = vr[1];
            acc[0] += p * v0.x; acc[1] += p * v0.y;
            acc[2] += p * v0.z; acc[3] += p * v0.w;
            acc[4] += p * v1.x; acc[5] += p * v1.y;
            acc[6] += p * v1.z; acc[7] += p * v1.w;
        }
        float sinv = Row[qi];
        int srow = q0 + qi;
        float* cptr = g_ctx + (size_t)(r * S_DIM + srow) * HD_DIM + h * D_DIM + dg * 8;
        const float* gptr = gb + srow * HD_DIM + dg * 8;
        #pragma unroll
        for (int u = 0; u < 8; u++) cptr[u] = acc[u] * sinv * gptr[u];
        __syncthreads();   // before Qs/Ls reuse
    }
}

// ============================================================
// Kernel 4: out projection + transpose scatter.
// ctx [65536 x 256] @ Wo [256 x 256] + bo -> out[s][r][c]
// row m = r*256 + s  ->  out index ((m&255)*256 + (m>>8))*256 + c
// ============================================================
__global__ void __launch_bounds__(256) outproj_gemm(
    const float* __restrict__ Wo, const float* __restrict__ bo,
    float* __restrict__ out)
{
    __shared__ float As[8][128];
    __shared__ float Bs[8][128];

    int tid = threadIdx.x;
    int tx = tid & 15;
    int ty = tid >> 4;
    int block_m = blockIdx.y * 128;
    int block_n = blockIdx.x * 128;

    int a_row = tid >> 1;
    int a_col = (tid & 1) * 4;
    int b_row = tid >> 5;
    int b_col = (tid & 31) * 4;

    float acc[8][8];
    #pragma unroll
    for (int i = 0; i < 8; i++)
        #pragma unroll
        for (int j = 0; j < 8; j++) acc[i][j] = 0.f;

    for (int k0 = 0; k0 < 256; k0 += 8) {
        float4 av = *(const float4*)(g_ctx + (size_t)(block_m + a_row) * 256 + k0 + a_col);
        As[a_col + 0][a_row] = av.x;
        As[a_col + 1][a_row] = av.y;
        As[a_col + 2][a_row] = av.z;
        As[a_col + 3][a_row] = av.w;
        *(float4*)(&Bs[b_row][b_col]) =
            *(const float4*)(Wo + (k0 + b_row) * 256 + block_n + b_col);
        __syncthreads();

        #pragma unroll
        for (int kk = 0; kk < 8; kk++) {
            float a[8], b[8];
            *(float4*)(a)     = *(const float4*)(&As[kk][ty * 8]);
            *(float4*)(a + 4) = *(const float4*)(&As[kk][ty * 8 + 4]);
            *(float4*)(b)     = *(const float4*)(&Bs[kk][tx * 8]);
            *(float4*)(b + 4) = *(const float4*)(&Bs[kk][tx * 8 + 4]);
            #pragma unroll
            for (int i = 0; i < 8; i++)
                #pragma unroll
                for (int j = 0; j < 8; j++)
                    acc[i][j] += a[i] * b[j];
        }
        __syncthreads();
    }

    int n0 = block_n + tx * 8;
    #pragma unroll
    for (int i = 0; i < 8; i++) {
        int m = block_m + ty * 8 + i;
        int r = m >> 8;
        int s = m & 255;
        float* orow = out + ((size_t)s * R_DIM + r) * C_DIM + n0;
        float vals[8];
        #pragma unroll
        for (int j = 0; j < 8; j++) vals[j] = acc[i][j] + bo[n0 + j];
        *(float4*)(orow)     = *(float4*)(vals);
        *(float4*)(orow + 4) = *(float4*)(vals + 4);
    }
}

// ============================================================
extern "C" void kernel_launch(void* const* d_in, const int* in_sizes, int n_in,
                              void* d_out, int out_size)
{
    const float* msa = (const float*)d_in[0];
    const float* lnw = (const float*)d_in[1];
    const float* lnb = (const float*)d_in[2];
    const float* Wq  = (const float*)d_in[3];
    const float* Wk  = (const float*)d_in[4];
    const float* Wv  = (const float*)d_in[5];
    const float* Wg  = (const float*)d_in[6];
    const float* bg  = (const float*)d_in[7];
    const float* Wo  = (const float*)d_in[8];
    const float* bo  = (const float*)d_in[9];
    float* out = (float*)d_out;

    ln_kernel<<<R_DIM, 256>>>(msa, lnw, lnb);

    qkvg_gemm<<<dim3(2, 512, 4), 256>>>(Wq, Wk, Wv, Wg, bg);

    cudaFuncSetAttribute(attn_kernel,
                         cudaFuncAttributeMaxDynamicSharedMemorySize, ATTN_SMEM);
    attn_kernel<<<dim3(H_DIM, R_DIM), 256, ATTN_SMEM>>>();

    outproj_gemm<<<dim3(2, 512, 1), 256>>>(Wo, bo, out);
}